// round 1
// baseline (speedup 1.0000x reference)
#include <cuda_runtime.h>
#include <cuda_bf16.h>
#include <math.h>

// Problem constants (shapes fixed by the dataset)
#define BATCH 4
#define NCTX  2048
#define DIM   1024
#define MTOT  (BATCH * NCTX)   // 8192

// Tiling
#define BM 128
#define BN 128
#define BK 16
#define TM 8
#define TN 8

// Scratch (device globals: allocation-free per harness rules)
__device__ float g_q[MTOT * DIM];
__device__ float g_k[MTOT * DIM];
__device__ float g_v[MTOT * DIM];
__device__ float g_s[(long)BATCH * NCTX * NCTX];

// ---------------------------------------------------------------------------
// NN GEMM: C[M,N] = A[M,K] @ B[K,N], row-major, optional causal k-limit
// (used for QKV projections and for P@V)
// ---------------------------------------------------------------------------
__global__ __launch_bounds__(256, 2)
void gemm_nn(const float* __restrict__ A, const float* __restrict__ B,
             float* __restrict__ C,
             int M, int N, int K,
             long sA, long sB, long sC, int causal_limit)
{
    const int b  = blockIdx.z;
    A += (long)b * sA;
    B += (long)b * sB;
    C += (long)b * sC;

    const int m0 = blockIdx.y * BM;
    const int n0 = blockIdx.x * BN;
    const int kend = causal_limit ? min(K, m0 + BM) : K;

    __shared__ float As[BM][BK + 1];   // [m][k], padded
    __shared__ float Bs[BK][BN];       // [k][n]

    const int tid = threadIdx.x;
    const int tx = tid & 15;
    const int ty = tid >> 4;

    // A-tile load indices: float4 along K
    const int a_row = tid >> 2;          // 0..63 (+64)
    const int a_k4  = (tid & 3) * 4;     // 0,4,8,12
    // B-tile load indices: float4 along N
    const int b_kr  = tid >> 5;          // 0..7 (+8)
    const int b_n4  = (tid & 31) * 4;    // 0..124

    float acc[TM][TN];
#pragma unroll
    for (int i = 0; i < TM; i++)
#pragma unroll
        for (int j = 0; j < TN; j++) acc[i][j] = 0.f;

    for (int k0 = 0; k0 < kend; k0 += BK) {
#pragma unroll
        for (int r = 0; r < 2; r++) {
            const int row = a_row + r * 64;
            float4 v4 = *(const float4*)&A[(long)(m0 + row) * K + k0 + a_k4];
            As[row][a_k4 + 0] = v4.x;
            As[row][a_k4 + 1] = v4.y;
            As[row][a_k4 + 2] = v4.z;
            As[row][a_k4 + 3] = v4.w;
        }
#pragma unroll
        for (int r = 0; r < 2; r++) {
            const int kr = b_kr + r * 8;
            *(float4*)&Bs[kr][b_n4] =
                *(const float4*)&B[(long)(k0 + kr) * N + n0 + b_n4];
        }
        __syncthreads();

#pragma unroll
        for (int kk = 0; kk < BK; kk++) {
            float a[TM], bb[TN];
#pragma unroll
            for (int i = 0; i < TM; i++) a[i] = As[i * 16 + ty][kk];
#pragma unroll
            for (int j = 0; j < TN; j++) bb[j] = Bs[kk][j * 16 + tx];
#pragma unroll
            for (int i = 0; i < TM; i++)
#pragma unroll
                for (int j = 0; j < TN; j++)
                    acc[i][j] = fmaf(a[i], bb[j], acc[i][j]);
        }
        __syncthreads();
    }

#pragma unroll
    for (int i = 0; i < TM; i++) {
        const long crow = (long)(m0 + i * 16 + ty) * N + n0;
#pragma unroll
        for (int j = 0; j < TN; j++)
            C[crow + j * 16 + tx] = acc[i][j];
    }
}

// ---------------------------------------------------------------------------
// NT GEMM for scores: S[m,n] = scale * sum_d Q[m,d] * K[n,d]
// Both Q and K row-major [NCTX, DIM]. Tiles fully above the diagonal skipped.
// No masking here: softmax only reads j<=m and zeroes the diagonal-tile pad.
// ---------------------------------------------------------------------------
__global__ __launch_bounds__(256, 2)
void gemm_nt_scores(const float* __restrict__ Q, const float* __restrict__ Kmat,
                    float* __restrict__ S, float scale)
{
    if (blockIdx.x > blockIdx.y) return;   // tile entirely above diagonal

    const int b  = blockIdx.z;
    const float* A = Q    + (long)b * NCTX * DIM;
    const float* B = Kmat + (long)b * NCTX * DIM;
    float*       C = S    + (long)b * NCTX * NCTX;

    const int m0 = blockIdx.y * BM;
    const int n0 = blockIdx.x * BN;

    __shared__ float As[BM][BK + 1];   // [m][k]
    __shared__ float Bs[BN][BK + 1];   // [n][k]

    const int tid = threadIdx.x;
    const int tx = tid & 15;
    const int ty = tid >> 4;

    const int l_row = tid >> 2;          // 0..63 (+64)
    const int l_k4  = (tid & 3) * 4;

    float acc[TM][TN];
#pragma unroll
    for (int i = 0; i < TM; i++)
#pragma unroll
        for (int j = 0; j < TN; j++) acc[i][j] = 0.f;

    for (int k0 = 0; k0 < DIM; k0 += BK) {
#pragma unroll
        for (int r = 0; r < 2; r++) {
            const int row = l_row + r * 64;
            float4 va = *(const float4*)&A[(long)(m0 + row) * DIM + k0 + l_k4];
            As[row][l_k4 + 0] = va.x;
            As[row][l_k4 + 1] = va.y;
            As[row][l_k4 + 2] = va.z;
            As[row][l_k4 + 3] = va.w;
            float4 vb = *(const float4*)&B[(long)(n0 + row) * DIM + k0 + l_k4];
            Bs[row][l_k4 + 0] = vb.x;
            Bs[row][l_k4 + 1] = vb.y;
            Bs[row][l_k4 + 2] = vb.z;
            Bs[row][l_k4 + 3] = vb.w;
        }
        __syncthreads();

#pragma unroll
        for (int kk = 0; kk < BK; kk++) {
            float a[TM], bb[TN];
#pragma unroll
            for (int i = 0; i < TM; i++) a[i] = As[i * 16 + ty][kk];
#pragma unroll
            for (int j = 0; j < TN; j++) bb[j] = Bs[j * 16 + tx][kk];
#pragma unroll
            for (int i = 0; i < TM; i++)
#pragma unroll
                for (int j = 0; j < TN; j++)
                    acc[i][j] = fmaf(a[i], bb[j], acc[i][j]);
        }
        __syncthreads();
    }

#pragma unroll
    for (int i = 0; i < TM; i++) {
        const long crow = (long)(m0 + i * 16 + ty) * NCTX + n0;
#pragma unroll
        for (int j = 0; j < TN; j++)
            C[crow + j * 16 + tx] = acc[i][j] * scale;
    }
}

// ---------------------------------------------------------------------------
// Causal row softmax, in place on S. Row m: softmax over j in [0, m];
// zero the pad j in (m, ceil128(m+1)) so the PV GEMM's k-limited loop is exact.
// ---------------------------------------------------------------------------
__global__ __launch_bounds__(256)
void softmax_causal(float* __restrict__ S)
{
    const int m = blockIdx.x;
    const int b = blockIdx.y;
    float* row = S + ((long)b * NCTX + m) * NCTX;
    const int len = m + 1;

    __shared__ float red[32];
    const int lane = threadIdx.x & 31;
    const int wid  = threadIdx.x >> 5;

    // --- max ---
    float mx = -1e30f;
    for (int j = threadIdx.x; j < len; j += blockDim.x)
        mx = fmaxf(mx, row[j]);
#pragma unroll
    for (int o = 16; o; o >>= 1) mx = fmaxf(mx, __shfl_xor_sync(~0u, mx, o));
    if (lane == 0) red[wid] = mx;
    __syncthreads();
    mx = (threadIdx.x < 8) ? red[threadIdx.x] : -1e30f;
    if (wid == 0) {
#pragma unroll
        for (int o = 4; o; o >>= 1) mx = fmaxf(mx, __shfl_xor_sync(~0u, mx, o));
        if (lane == 0) red[0] = mx;
    }
    __syncthreads();
    mx = red[0];
    __syncthreads();

    // --- exp + sum ---
    float sum = 0.f;
    for (int j = threadIdx.x; j < len; j += blockDim.x) {
        float e = expf(row[j] - mx);
        row[j] = e;
        sum += e;
    }
#pragma unroll
    for (int o = 16; o; o >>= 1) sum += __shfl_xor_sync(~0u, sum, o);
    if (lane == 0) red[wid] = sum;
    __syncthreads();
    sum = (threadIdx.x < 8) ? red[threadIdx.x] : 0.f;
    if (wid == 0) {
#pragma unroll
        for (int o = 4; o; o >>= 1) sum += __shfl_xor_sync(~0u, sum, o);
        if (lane == 0) red[0] = sum;
    }
    __syncthreads();
    const float inv = 1.f / red[0];

    for (int j = threadIdx.x; j < len; j += blockDim.x)
        row[j] *= inv;

    // zero pad up to the end of the diagonal 128-tile
    const int pad_end = ((m >> 7) + 1) << 7;
    for (int j = len + threadIdx.x; j < pad_end; j += blockDim.x)
        row[j] = 0.f;
}

// ---------------------------------------------------------------------------
extern "C" void kernel_launch(void* const* d_in, const int* in_sizes, int n_in,
                              void* d_out, int out_size)
{
    const float* x  = (const float*)d_in[0];
    const float* Wq = (const float*)d_in[1];
    const float* Wk = (const float*)d_in[2];
    const float* Wv = (const float*)d_in[3];
    float* out = (float*)d_out;

    float *q, *k, *v, *s;
    cudaGetSymbolAddress((void**)&q, g_q);
    cudaGetSymbolAddress((void**)&k, g_k);
    cudaGetSymbolAddress((void**)&v, g_v);
    cudaGetSymbolAddress((void**)&s, g_s);

    const dim3 blk(256);

    // 1) QKV projections: [8192,1024] @ [1024,1024]
    const dim3 gproj(DIM / BN, MTOT / BM, 1);
    gemm_nn<<<gproj, blk>>>(x, Wq, q, MTOT, DIM, DIM, 0, 0, 0, 0);
    gemm_nn<<<gproj, blk>>>(x, Wk, k, MTOT, DIM, DIM, 0, 0, 0, 0);
    gemm_nn<<<gproj, blk>>>(x, Wv, v, MTOT, DIM, DIM, 0, 0, 0, 0);

    // 2) Scores: S = scale * Q @ K^T, causal tile skip
    const float scale = 1.0f / sqrtf((float)DIM);   // 0.03125
    const dim3 gsc(NCTX / BN, NCTX / BM, BATCH);
    gemm_nt_scores<<<gsc, blk>>>(q, k, s, scale);

    // 3) Causal softmax (in place, zeroes diagonal-tile pad)
    softmax_causal<<<dim3(NCTX, BATCH), blk>>>(s);

    // 4) O = P @ V with causal k-limit
    const dim3 gpv(DIM / BN, NCTX / BM, BATCH);
    gemm_nn<<<gpv, blk>>>(s, v, out, NCTX, DIM, NCTX,
                          (long)NCTX * NCTX, (long)NCTX * DIM,
                          (long)NCTX * DIM, 1);
}

// round 2
// speedup vs baseline: 3.0411x; 3.0411x over previous
#include <cuda_runtime.h>
#include <cuda_bf16.h>
#include <math.h>
#include <stdint.h>

// Problem constants
#define BATCH 4
#define NCTX  2048
#define DIM   1024
#define MTOT  (BATCH * NCTX)   // 8192

// Tiling
#define BM 128
#define BN 128
#define BK 32
#define SA 36      // A-tile smem stride (floats): (36*row)%32 = 4*row -> conflict-free frags
#define SBNN 136   // B-tile smem stride for NN: (136*k)%32 = 8*k -> conflict-free frags

// Scratch
__device__ float g_q[MTOT * DIM];
__device__ float g_k[MTOT * DIM];
__device__ float g_v[MTOT * DIM];
__device__ float g_s[(long)BATCH * NCTX * NCTX];

// ---------------------------------------------------------------------------
__device__ __forceinline__ uint32_t f2tf32(float f) {
    uint32_t u;
    asm("cvt.rna.tf32.f32 %0, %1;" : "=r"(u) : "f"(f));
    return u;
}

__device__ __forceinline__ void mma8(float* c,
                                     uint32_t a0, uint32_t a1, uint32_t a2, uint32_t a3,
                                     uint32_t b0, uint32_t b1) {
    asm volatile(
        "mma.sync.aligned.m16n8k8.row.col.f32.tf32.tf32.f32 "
        "{%0,%1,%2,%3}, {%4,%5,%6,%7}, {%8,%9}, {%0,%1,%2,%3};\n"
        : "+f"(c[0]), "+f"(c[1]), "+f"(c[2]), "+f"(c[3])
        : "r"(a0), "r"(a1), "r"(a2), "r"(a3), "r"(b0), "r"(b1));
}

// ---------------------------------------------------------------------------
// Fused QKV projection: z selects (Wq->q, Wk->k, Wv->v). C = X @ W, all NN.
// X: [MTOT, DIM], W: [DIM, DIM].
// ---------------------------------------------------------------------------
__global__ __launch_bounds__(256, 2)
void gemm_qkv(const float* __restrict__ X,
              const float* __restrict__ Wq, const float* __restrict__ Wk,
              const float* __restrict__ Wv,
              float* __restrict__ Q, float* __restrict__ Ko, float* __restrict__ V)
{
    const float* B = (blockIdx.z == 0) ? Wq : (blockIdx.z == 1) ? Wk : Wv;
    float*       C = (blockIdx.z == 0) ? Q  : (blockIdx.z == 1) ? Ko : V;
    const int m0 = blockIdx.y * BM;
    const int n0 = blockIdx.x * BN;
    const int N = DIM, K = DIM;

    __shared__ float As[BM][SA];
    __shared__ float Bs[BK][SBNN];

    const int tid  = threadIdx.x;
    const int lane = tid & 31;
    const int wid  = tid >> 5;
    const int g  = lane >> 2;
    const int tg = lane & 3;
    const int wm = (wid >> 1) * 32;
    const int wn = (wid & 1) * 64;

    float c[2][8][4];
#pragma unroll
    for (int mi = 0; mi < 2; mi++)
#pragma unroll
        for (int ni = 0; ni < 8; ni++)
#pragma unroll
            for (int r = 0; r < 4; r++) c[mi][ni][r] = 0.f;

    for (int k0 = 0; k0 < K; k0 += BK) {
#pragma unroll
        for (int i = 0; i < 4; i++) {
            int idx = tid + i * 256;
            int row = idx >> 3;
            int c4  = (idx & 7) << 2;
            *(float4*)&As[row][c4] =
                *(const float4*)&X[(long)(m0 + row) * K + k0 + c4];
        }
#pragma unroll
        for (int i = 0; i < 4; i++) {
            int idx = tid + i * 256;
            int kr = idx >> 5;
            int n4 = (idx & 31) << 2;
            *(float4*)&Bs[kr][n4] =
                *(const float4*)&B[(long)(k0 + kr) * N + n0 + n4];
        }
        __syncthreads();

#pragma unroll
        for (int ks = 0; ks < 4; ks++) {
            const int kb = ks * 8;
            uint32_t a[2][4];
#pragma unroll
            for (int mi = 0; mi < 2; mi++) {
                int r = wm + mi * 16 + g;
                a[mi][0] = f2tf32(As[r][kb + tg]);
                a[mi][1] = f2tf32(As[r + 8][kb + tg]);
                a[mi][2] = f2tf32(As[r][kb + tg + 4]);
                a[mi][3] = f2tf32(As[r + 8][kb + tg + 4]);
            }
#pragma unroll
            for (int ni = 0; ni < 8; ni++) {
                uint32_t b0 = f2tf32(Bs[kb + tg][wn + ni * 8 + g]);
                uint32_t b1 = f2tf32(Bs[kb + tg + 4][wn + ni * 8 + g]);
                mma8(c[0][ni], a[0][0], a[0][1], a[0][2], a[0][3], b0, b1);
                mma8(c[1][ni], a[1][0], a[1][1], a[1][2], a[1][3], b0, b1);
            }
        }
        __syncthreads();
    }

#pragma unroll
    for (int mi = 0; mi < 2; mi++) {
        const int row0 = m0 + wm + mi * 16 + g;
#pragma unroll
        for (int ni = 0; ni < 8; ni++) {
            const int col = n0 + wn + ni * 8 + tg * 2;
            *(float2*)&C[(long)row0 * N + col]       = make_float2(c[mi][ni][0], c[mi][ni][1]);
            *(float2*)&C[(long)(row0 + 8) * N + col] = make_float2(c[mi][ni][2], c[mi][ni][3]);
        }
    }
}

// ---------------------------------------------------------------------------
// Scores: S = scale * Q @ K^T  (NT, both K-major), causal tile skip.
// ---------------------------------------------------------------------------
__global__ __launch_bounds__(256, 2)
void gemm_nt_scores(const float* __restrict__ Qm, const float* __restrict__ Km,
                    float* __restrict__ S, float scale)
{
    if (blockIdx.x > blockIdx.y) return;

    const int b = blockIdx.z;
    const float* A = Qm + (long)b * NCTX * DIM;
    const float* B = Km + (long)b * NCTX * DIM;
    float*       C = S  + (long)b * NCTX * NCTX;

    const int m0 = blockIdx.y * BM;
    const int n0 = blockIdx.x * BN;

    __shared__ float As[BM][SA];
    __shared__ float Bs[BN][SA];

    const int tid  = threadIdx.x;
    const int lane = tid & 31;
    const int wid  = tid >> 5;
    const int g  = lane >> 2;
    const int tg = lane & 3;
    const int wm = (wid >> 1) * 32;
    const int wn = (wid & 1) * 64;

    float c[2][8][4];
#pragma unroll
    for (int mi = 0; mi < 2; mi++)
#pragma unroll
        for (int ni = 0; ni < 8; ni++)
#pragma unroll
            for (int r = 0; r < 4; r++) c[mi][ni][r] = 0.f;

    for (int k0 = 0; k0 < DIM; k0 += BK) {
#pragma unroll
        for (int i = 0; i < 4; i++) {
            int idx = tid + i * 256;
            int row = idx >> 3;
            int c4  = (idx & 7) << 2;
            *(float4*)&As[row][c4] =
                *(const float4*)&A[(long)(m0 + row) * DIM + k0 + c4];
            *(float4*)&Bs[row][c4] =
                *(const float4*)&B[(long)(n0 + row) * DIM + k0 + c4];
        }
        __syncthreads();

#pragma unroll
        for (int ks = 0; ks < 4; ks++) {
            const int kb = ks * 8;
            uint32_t a[2][4];
#pragma unroll
            for (int mi = 0; mi < 2; mi++) {
                int r = wm + mi * 16 + g;
                a[mi][0] = f2tf32(As[r][kb + tg]);
                a[mi][1] = f2tf32(As[r + 8][kb + tg]);
                a[mi][2] = f2tf32(As[r][kb + tg + 4]);
                a[mi][3] = f2tf32(As[r + 8][kb + tg + 4]);
            }
#pragma unroll
            for (int ni = 0; ni < 8; ni++) {
                int nr = wn + ni * 8 + g;
                uint32_t b0 = f2tf32(Bs[nr][kb + tg]);
                uint32_t b1 = f2tf32(Bs[nr][kb + tg + 4]);
                mma8(c[0][ni], a[0][0], a[0][1], a[0][2], a[0][3], b0, b1);
                mma8(c[1][ni], a[1][0], a[1][1], a[1][2], a[1][3], b0, b1);
            }
        }
        __syncthreads();
    }

#pragma unroll
    for (int mi = 0; mi < 2; mi++) {
        const int row0 = m0 + wm + mi * 16 + g;
#pragma unroll
        for (int ni = 0; ni < 8; ni++) {
            const int col = n0 + wn + ni * 8 + tg * 2;
            *(float2*)&C[(long)row0 * NCTX + col] =
                make_float2(c[mi][ni][0] * scale, c[mi][ni][1] * scale);
            *(float2*)&C[(long)(row0 + 8) * NCTX + col] =
                make_float2(c[mi][ni][2] * scale, c[mi][ni][3] * scale);
        }
    }
}

// ---------------------------------------------------------------------------
// PV: O = P @ V (NN) with causal k-limit per row-tile.
// ---------------------------------------------------------------------------
__global__ __launch_bounds__(256, 2)
void gemm_pv(const float* __restrict__ P, const float* __restrict__ V,
             float* __restrict__ O)
{
    const int b = blockIdx.z;
    const float* A = P + (long)b * NCTX * NCTX;
    const float* B = V + (long)b * NCTX * DIM;
    float*       C = O + (long)b * NCTX * DIM;

    const int m0 = blockIdx.y * BM;
    const int n0 = blockIdx.x * BN;
    const int N = DIM, K = NCTX;
    const int kend = min(K, m0 + BM);

    __shared__ float As[BM][SA];
    __shared__ float Bs[BK][SBNN];

    const int tid  = threadIdx.x;
    const int lane = tid & 31;
    const int wid  = tid >> 5;
    const int g  = lane >> 2;
    const int tg = lane & 3;
    const int wm = (wid >> 1) * 32;
    const int wn = (wid & 1) * 64;

    float c[2][8][4];
#pragma unroll
    for (int mi = 0; mi < 2; mi++)
#pragma unroll
        for (int ni = 0; ni < 8; ni++)
#pragma unroll
            for (int r = 0; r < 4; r++) c[mi][ni][r] = 0.f;

    for (int k0 = 0; k0 < kend; k0 += BK) {
#pragma unroll
        for (int i = 0; i < 4; i++) {
            int idx = tid + i * 256;
            int row = idx >> 3;
            int c4  = (idx & 7) << 2;
            *(float4*)&As[row][c4] =
                *(const float4*)&A[(long)(m0 + row) * K + k0 + c4];
        }
#pragma unroll
        for (int i = 0; i < 4; i++) {
            int idx = tid + i * 256;
            int kr = idx >> 5;
            int n4 = (idx & 31) << 2;
            *(float4*)&Bs[kr][n4] =
                *(const float4*)&B[(long)(k0 + kr) * N + n0 + n4];
        }
        __syncthreads();

#pragma unroll
        for (int ks = 0; ks < 4; ks++) {
            const int kb = ks * 8;
            uint32_t a[2][4];
#pragma unroll
            for (int mi = 0; mi < 2; mi++) {
                int r = wm + mi * 16 + g;
                a[mi][0] = f2tf32(As[r][kb + tg]);
                a[mi][1] = f2tf32(As[r + 8][kb + tg]);
                a[mi][2] = f2tf32(As[r][kb + tg + 4]);
                a[mi][3] = f2tf32(As[r + 8][kb + tg + 4]);
            }
#pragma unroll
            for (int ni = 0; ni < 8; ni++) {
                uint32_t b0 = f2tf32(Bs[kb + tg][wn + ni * 8 + g]);
                uint32_t b1 = f2tf32(Bs[kb + tg + 4][wn + ni * 8 + g]);
                mma8(c[0][ni], a[0][0], a[0][1], a[0][2], a[0][3], b0, b1);
                mma8(c[1][ni], a[1][0], a[1][1], a[1][2], a[1][3], b0, b1);
            }
        }
        __syncthreads();
    }

#pragma unroll
    for (int mi = 0; mi < 2; mi++) {
        const int row0 = m0 + wm + mi * 16 + g;
#pragma unroll
        for (int ni = 0; ni < 8; ni++) {
            const int col = n0 + wn + ni * 8 + tg * 2;
            *(float2*)&C[(long)row0 * N + col]       = make_float2(c[mi][ni][0], c[mi][ni][1]);
            *(float2*)&C[(long)(row0 + 8) * N + col] = make_float2(c[mi][ni][2], c[mi][ni][3]);
        }
    }
}

// ---------------------------------------------------------------------------
// Causal row softmax, in place; zeroes pad up to end of diagonal 128-tile.
// ---------------------------------------------------------------------------
__global__ __launch_bounds__(256)
void softmax_causal(float* __restrict__ S)
{
    const int m = blockIdx.x;
    const int b = blockIdx.y;
    float* row = S + ((long)b * NCTX + m) * NCTX;
    const int len = m + 1;

    __shared__ float red[32];
    const int lane = threadIdx.x & 31;
    const int wid  = threadIdx.x >> 5;

    float mx = -1e30f;
    for (int j = threadIdx.x; j < len; j += blockDim.x)
        mx = fmaxf(mx, row[j]);
#pragma unroll
    for (int o = 16; o; o >>= 1) mx = fmaxf(mx, __shfl_xor_sync(~0u, mx, o));
    if (lane == 0) red[wid] = mx;
    __syncthreads();
    mx = (threadIdx.x < 8) ? red[threadIdx.x] : -1e30f;
    if (wid == 0) {
#pragma unroll
        for (int o = 4; o; o >>= 1) mx = fmaxf(mx, __shfl_xor_sync(~0u, mx, o));
        if (lane == 0) red[0] = mx;
    }
    __syncthreads();
    mx = red[0];
    __syncthreads();

    float sum = 0.f;
    for (int j = threadIdx.x; j < len; j += blockDim.x) {
        float e = expf(row[j] - mx);
        row[j] = e;
        sum += e;
    }
#pragma unroll
    for (int o = 16; o; o >>= 1) sum += __shfl_xor_sync(~0u, sum, o);
    if (lane == 0) red[wid] = sum;
    __syncthreads();
    sum = (threadIdx.x < 8) ? red[threadIdx.x] : 0.f;
    if (wid == 0) {
#pragma unroll
        for (int o = 4; o; o >>= 1) sum += __shfl_xor_sync(~0u, sum, o);
        if (lane == 0) red[0] = sum;
    }
    __syncthreads();
    const float inv = 1.f / red[0];

    for (int j = threadIdx.x; j < len; j += blockDim.x)
        row[j] *= inv;

    const int pad_end = ((m >> 7) + 1) << 7;
    for (int j = len + threadIdx.x; j < pad_end; j += blockDim.x)
        row[j] = 0.f;
}

// ---------------------------------------------------------------------------
extern "C" void kernel_launch(void* const* d_in, const int* in_sizes, int n_in,
                              void* d_out, int out_size)
{
    const float* x  = (const float*)d_in[0];
    const float* Wq = (const float*)d_in[1];
    const float* Wk = (const float*)d_in[2];
    const float* Wv = (const float*)d_in[3];
    float* out = (float*)d_out;

    float *q, *k, *v, *s;
    cudaGetSymbolAddress((void**)&q, g_q);
    cudaGetSymbolAddress((void**)&k, g_k);
    cudaGetSymbolAddress((void**)&v, g_v);
    cudaGetSymbolAddress((void**)&s, g_s);

    const dim3 blk(256);

    // 1) QKV projections (fused launch, z = q/k/v)
    gemm_qkv<<<dim3(DIM / BN, MTOT / BM, 3), blk>>>(x, Wq, Wk, Wv, q, k, v);

    // 2) Scores with causal tile skip
    const float scale = 1.0f / sqrtf((float)DIM);
    gemm_nt_scores<<<dim3(NCTX / BN, NCTX / BM, BATCH), blk>>>(q, k, s, scale);

    // 3) Causal softmax (zeroes diagonal-tile pad)
    softmax_causal<<<dim3(NCTX, BATCH), blk>>>(s);

    // 4) O = P @ V with causal k-limit
    gemm_pv<<<dim3(DIM / BN, NCTX / BM, BATCH), blk>>>(s, v, out);
}